// round 15
// baseline (speedup 1.0000x reference)
#include <cuda_runtime.h>
#include <cuda_fp16.h>
#include <cstdint>

#define N_NODES 100000
#define N_EDGES 3200000
#define IN_DIM  256
#define OUT_DIM 128
#define CAP     96      // bucket capacity; Poisson(32) max-degree << 96

// ---------------- static scratch (no allocations allowed) ------------------
__device__ __half g_xw[(size_t)N_NODES * OUT_DIM];     // 25.6 MB  x @ W (fp16)
__device__ int2   g_bucket[(size_t)N_NODES * CAP];     // 76.8 MB  {src, w bits}
__device__ int    g_cur[N_NODES];                      // cursors; zero-init, and
                                                       // gather resets them -> no zcur kernel

// ---------------------------------------------------------------------------
// TF32 tensor-core GEMM  xw[M,128] = x[M,256] @ W[256,128], fp16 output.
// BM=128, BN=128, BK=32; 8 warps = 2M x 4N; warp tile 64x32.
// cp.async DOUBLE-BUFFERED smem (raw fp32), cvt.rna.tf32 at fragment load.
// (Proven R13 config.)
// ---------------------------------------------------------------------------
#define BM 128
#define BK 32
#define A_PITCH 36
#define B_PITCH 136
#define A_WORDS (BM * A_PITCH)              // 4608
#define B_WORDS (BK * B_PITCH)              // 4352
#define BUF_WORDS (A_WORDS + B_WORDS)       // 8960
#define GEMM_SMEM_BYTES (2 * BUF_WORDS * 4) // 71680

__device__ __forceinline__ uint32_t f2tf32(float f) {
    uint32_t r;
    asm("cvt.rna.tf32.f32 %0, %1;" : "=r"(r) : "f"(f));
    return r;
}

__device__ __forceinline__ void cp16(uint32_t dst_smem, const void* src, bool pred) {
    asm volatile("cp.async.cg.shared.global [%0], [%1], 16, %2;"
                 :: "r"(dst_smem), "l"(src), "r"(pred ? 16 : 0));
}

__global__ __launch_bounds__(256, 2) void gemm_tf32_kernel(const float* __restrict__ x,
                                                           const float* __restrict__ w) {
    extern __shared__ float sm[];

    const int tid    = threadIdx.x;
    const int wid    = tid >> 5;
    const int lane   = tid & 31;
    const int grp    = lane >> 2;
    const int qid    = lane & 3;
    const int warp_m = wid >> 2;
    const int warp_n = wid & 3;
    const int m0     = blockIdx.x * BM;
    const int m_base = warp_m * 64;
    const int n_base = warp_n * 32;

    const int a_kc = tid & 7;
    const int b_nc = tid & 31;

    auto issue_tile = [&](int k0, int buf) {
        float* base = sm + buf * BUF_WORDS;
        uint32_t a_base = (uint32_t)__cvta_generic_to_shared(base);
        uint32_t b_base = (uint32_t)__cvta_generic_to_shared(base + A_WORDS);
#pragma unroll
        for (int it = 0; it < 4; it++) {
            int s   = tid + it * 256;
            int m   = s >> 3;
            int row = m0 + m;
            bool ok = row < N_NODES;
            int srow = ok ? row : (N_NODES - 1);
            cp16(a_base + (uint32_t)(m * A_PITCH + a_kc * 4) * 4,
                 x + (size_t)srow * IN_DIM + k0 + a_kc * 4, ok);
        }
#pragma unroll
        for (int it = 0; it < 4; it++) {
            int s = tid + it * 256;
            int k = s >> 5;
            cp16(b_base + (uint32_t)(k * B_PITCH + b_nc * 4) * 4,
                 w + (size_t)(k0 + k) * OUT_DIM + b_nc * 4, true);
        }
        asm volatile("cp.async.commit_group;");
    };

    float c[4][4][4];
#pragma unroll
    for (int mt = 0; mt < 4; mt++)
#pragma unroll
        for (int nt = 0; nt < 4; nt++)
#pragma unroll
            for (int r = 0; r < 4; r++) c[mt][nt][r] = 0.f;

    issue_tile(0, 0);
    asm volatile("cp.async.wait_group 0;");
    __syncthreads();

    int buf = 0;
    for (int k0 = 0; k0 < IN_DIM; k0 += BK) {
        const bool more = (k0 + BK) < IN_DIM;
        if (more) issue_tile(k0 + BK, buf ^ 1);

        const float* A = sm + buf * BUF_WORDS;
        const float* B = A + A_WORDS;

#pragma unroll
        for (int ks = 0; ks < 4; ks++) {
            const int kk = ks * 8;
            uint32_t a[4][4], b[4][2];
#pragma unroll
            for (int mt = 0; mt < 4; mt++) {
                int row = m_base + mt * 16 + grp;
                a[mt][0] = f2tf32(A[row * A_PITCH + kk + qid]);
                a[mt][1] = f2tf32(A[(row + 8) * A_PITCH + kk + qid]);
                a[mt][2] = f2tf32(A[row * A_PITCH + kk + qid + 4]);
                a[mt][3] = f2tf32(A[(row + 8) * A_PITCH + kk + qid + 4]);
            }
#pragma unroll
            for (int nt = 0; nt < 4; nt++) {
                int col = n_base + nt * 8 + grp;
                b[nt][0] = f2tf32(B[(kk + qid) * B_PITCH + col]);
                b[nt][1] = f2tf32(B[(kk + qid + 4) * B_PITCH + col]);
            }
#pragma unroll
            for (int mt = 0; mt < 4; mt++)
#pragma unroll
                for (int nt = 0; nt < 4; nt++) {
                    asm volatile(
                        "mma.sync.aligned.m16n8k8.row.col.f32.tf32.tf32.f32 "
                        "{%0,%1,%2,%3}, {%4,%5,%6,%7}, {%8,%9}, {%0,%1,%2,%3};\n"
                        : "+f"(c[mt][nt][0]), "+f"(c[mt][nt][1]),
                          "+f"(c[mt][nt][2]), "+f"(c[mt][nt][3])
                        : "r"(a[mt][0]), "r"(a[mt][1]), "r"(a[mt][2]), "r"(a[mt][3]),
                          "r"(b[nt][0]), "r"(b[nt][1]));
                }
        }
        if (more) {
            asm volatile("cp.async.wait_group 0;");
            __syncthreads();
            buf ^= 1;
        }
    }

#pragma unroll
    for (int mt = 0; mt < 4; mt++) {
        int r0 = m0 + m_base + mt * 16 + grp;
        int r1 = r0 + 8;
#pragma unroll
        for (int nt = 0; nt < 4; nt++) {
            int col = n_base + nt * 8 + qid * 2;
            if (r0 < N_NODES)
                *(__half2*)(g_xw + (size_t)r0 * OUT_DIM + col) =
                    __floats2half2_rn(c[mt][nt][0], c[mt][nt][1]);
            if (r1 < N_NODES)
                *(__half2*)(g_xw + (size_t)r1 * OUT_DIM + col) =
                    __floats2half2_rn(c[mt][nt][2], c[mt][nt][3]);
        }
    }
}

// ---------------------------------------------------------------------------
// Fill pass: cursors are zero on entry (zero-init at load; gather resets
// them at the end of every call). No separate zeroing kernel needed.
// ---------------------------------------------------------------------------
__global__ void fill_kernel(const int* __restrict__ esrc,
                            const int* __restrict__ edst,
                            const float* __restrict__ ew) {
    int e = blockIdx.x * blockDim.x + threadIdx.x;
    if (e < N_EDGES) {
        int d   = edst[e];
        int pos = atomicAdd(&g_cur[d], 1);
        if (pos < CAP)   // safety clamp; statistically unreachable
            g_bucket[(size_t)d * CAP + pos] = make_int2(esrc[e], __float_as_int(ew[e]));
    }
}

// ---------------------------------------------------------------------------
// Aggregate v5: one warp per dst node; 16 lanes x 16B per row (proven
// layout); edge-pair loop UNROLLED x4 -> 4 independent LDG.128 in flight
// per lane. Packed fma.rn.f32x2; zero-weight padding; cross-half shfl
// reduction; fused ReLU. Resets g_cur[node] for the next call. No atomics.
// ---------------------------------------------------------------------------
__global__ __launch_bounds__(256) void gather_kernel(float* __restrict__ out) {
    const int node = blockIdx.x * 8 + (threadIdx.x >> 5);
    const int lane = threadIdx.x & 31;
    if (node >= N_NODES) return;

    const int h   = lane >> 4;       // which edge of the pair
    const int sub = lane & 15;       // 16B chunk within the row

    const int cnt = min(g_cur[node], CAP);
    if (lane == 0 && cnt != 0) g_cur[node] = 0;   // self-reset for next call
    const int2* bkt = g_bucket + (size_t)node * CAP;

    unsigned long long acc[4] = {0ull, 0ull, 0ull, 0ull};   // 4 x f32x2

    for (int base = 0; base < cnt; base += 32) {
        const int n = min(32, cnt - base);
        int   mysrc = 0;
        float myw   = 0.f;                   // zero weight = inert padding
        if (lane < n) {
            int2 rec = bkt[base + lane];
            mysrc = rec.x;
            myw   = __int_as_float(rec.y);
        }
        const int jmax = (n + 1) >> 1;       // edge-pairs in this batch
        int jj = 0;
        // ---- unrolled x4: four independent gathers in flight ----
        for (; jj + 4 <= jmax; jj += 4) {
            const int   s0 = __shfl_sync(0xffffffff, mysrc, 2 * jj + 0 + h);
            const int   s1 = __shfl_sync(0xffffffff, mysrc, 2 * jj + 2 + h);
            const int   s2 = __shfl_sync(0xffffffff, mysrc, 2 * jj + 4 + h);
            const int   s3 = __shfl_sync(0xffffffff, mysrc, 2 * jj + 6 + h);
            const float w0 = __shfl_sync(0xffffffff, myw,  2 * jj + 0 + h);
            const float w1 = __shfl_sync(0xffffffff, myw,  2 * jj + 2 + h);
            const float w2 = __shfl_sync(0xffffffff, myw,  2 * jj + 4 + h);
            const float w3 = __shfl_sync(0xffffffff, myw,  2 * jj + 6 + h);

            const float4 r0 = *(const float4*)(g_xw + (size_t)s0 * OUT_DIM + sub * 8);
            const float4 r1 = *(const float4*)(g_xw + (size_t)s1 * OUT_DIM + sub * 8);
            const float4 r2 = *(const float4*)(g_xw + (size_t)s2 * OUT_DIM + sub * 8);
            const float4 r3 = *(const float4*)(g_xw + (size_t)s3 * OUT_DIM + sub * 8);

            unsigned long long ww0, ww1, ww2, ww3;
            asm("mov.b64 %0, {%1, %1};" : "=l"(ww0) : "f"(w0));
            asm("mov.b64 %0, {%1, %1};" : "=l"(ww1) : "f"(w1));
            asm("mov.b64 %0, {%1, %1};" : "=l"(ww2) : "f"(w2));
            asm("mov.b64 %0, {%1, %1};" : "=l"(ww3) : "f"(w3));

            const __half2* h0 = (const __half2*)&r0;
            const __half2* h1 = (const __half2*)&r1;
            const __half2* h2 = (const __half2*)&r2;
            const __half2* h3 = (const __half2*)&r3;
#pragma unroll
            for (int r = 0; r < 4; r++) {
                float2 v = __half22float2(h0[r]);
                unsigned long long vv;
                asm("mov.b64 %0, {%1, %2};" : "=l"(vv) : "f"(v.x), "f"(v.y));
                asm("fma.rn.f32x2 %0, %1, %2, %0;" : "+l"(acc[r]) : "l"(vv), "l"(ww0));
            }
#pragma unroll
            for (int r = 0; r < 4; r++) {
                float2 v = __half22float2(h1[r]);
                unsigned long long vv;
                asm("mov.b64 %0, {%1, %2};" : "=l"(vv) : "f"(v.x), "f"(v.y));
                asm("fma.rn.f32x2 %0, %1, %2, %0;" : "+l"(acc[r]) : "l"(vv), "l"(ww1));
            }
#pragma unroll
            for (int r = 0; r < 4; r++) {
                float2 v = __half22float2(h2[r]);
                unsigned long long vv;
                asm("mov.b64 %0, {%1, %2};" : "=l"(vv) : "f"(v.x), "f"(v.y));
                asm("fma.rn.f32x2 %0, %1, %2, %0;" : "+l"(acc[r]) : "l"(vv), "l"(ww2));
            }
#pragma unroll
            for (int r = 0; r < 4; r++) {
                float2 v = __half22float2(h3[r]);
                unsigned long long vv;
                asm("mov.b64 %0, {%1, %2};" : "=l"(vv) : "f"(v.x), "f"(v.y));
                asm("fma.rn.f32x2 %0, %1, %2, %0;" : "+l"(acc[r]) : "l"(vv), "l"(ww3));
            }
        }
        // ---- tail edge-pairs ----
        for (; jj < jmax; jj++) {
            const int   src = __shfl_sync(0xffffffff, mysrc, 2 * jj + h);
            const float wsc = __shfl_sync(0xffffffff, myw,  2 * jj + h);
            unsigned long long ww;
            asm("mov.b64 %0, {%1, %1};" : "=l"(ww) : "f"(wsc));
            const float4 raw = *(const float4*)(g_xw + (size_t)src * OUT_DIM + sub * 8);
            const __half2* hp = (const __half2*)&raw;
#pragma unroll
            for (int r = 0; r < 4; r++) {
                float2 v = __half22float2(hp[r]);
                unsigned long long vv;
                asm("mov.b64 %0, {%1, %2};" : "=l"(vv) : "f"(v.x), "f"(v.y));
                asm("fma.rn.f32x2 %0, %1, %2, %0;" : "+l"(acc[r]) : "l"(vv), "l"(ww));
            }
        }
    }

    // cross-half reduction (lane i += lane i+16), ReLU, store by lanes 0-15
    float lo[4], hi[4];
#pragma unroll
    for (int r = 0; r < 4; r++) {
        float2 a = *(float2*)&acc[r];
        a.x += __shfl_xor_sync(0xffffffff, a.x, 16);
        a.y += __shfl_xor_sync(0xffffffff, a.y, 16);
        lo[r] = fmaxf(a.x, 0.f);
        hi[r] = fmaxf(a.y, 0.f);
    }
    if (h == 0) {
        float* o = out + (size_t)node * OUT_DIM + sub * 8;
        *(float4*)(o + 0) = make_float4(lo[0], hi[0], lo[1], hi[1]);
        *(float4*)(o + 4) = make_float4(lo[2], hi[2], lo[3], hi[3]);
    }
}

// ---------------------------------------------------------------------------
extern "C" void kernel_launch(void* const* d_in, const int* in_sizes, int n_in,
                              void* d_out, int out_size) {
    const float* x  = (const float*)d_in[0];       // [100000, 256] f32
    const float* w  = (const float*)d_in[1];       // [256, 128]    f32
    const float* ew = (const float*)d_in[2];       // [3.2M]        f32
    const int*   es = (const int*)d_in[3];         // [3.2M]        i32
    const int*   ed = (const int*)d_in[4];         // [3.2M]        i32
    float* out = (float*)d_out;                    // [100000, 128] f32

    const int eBlocks = (N_EDGES + 255) / 256;     // 12500
    const int gBlocks = (N_NODES + BM - 1) / BM;   // 782
    const int aBlocks = (N_NODES + 7) / 8;         // 12500 (8 warps/block)

    // static side stream + events for GEMM || bucket-build overlap
    static cudaStream_t side = nullptr;
    static cudaEvent_t  evFork = nullptr, evJoin = nullptr;
    if (!side) {
        cudaStreamCreateWithFlags(&side, cudaStreamNonBlocking);
        cudaEventCreateWithFlags(&evFork, cudaEventDisableTiming);
        cudaEventCreateWithFlags(&evJoin, cudaEventDisableTiming);
        cudaFuncSetAttribute(gemm_tf32_kernel,
                             cudaFuncAttributeMaxDynamicSharedMemorySize,
                             GEMM_SMEM_BYTES);
    }

    // fork: GEMM on side stream
    cudaEventRecord(evFork, 0);
    cudaStreamWaitEvent(side, evFork, 0);
    gemm_tf32_kernel<<<gBlocks, 256, GEMM_SMEM_BYTES, side>>>(x, w);
    cudaEventRecord(evJoin, side);

    // bucket build on main stream (cursors already zero; fill only)
    fill_kernel<<<eBlocks, 256>>>(es, ed, ew);

    // join: gather needs both g_xw (side) and buckets (main)
    cudaStreamWaitEvent(0, evJoin, 0);
    gather_kernel<<<aBlocks, 256>>>(out);
}

// round 17
// speedup vs baseline: 1.4808x; 1.4808x over previous
#include <cuda_runtime.h>
#include <cuda_fp16.h>
#include <cstdint>

#define N_NODES 100000
#define N_EDGES 3200000
#define IN_DIM  256
#define OUT_DIM 128
#define CAP     96      // bucket capacity; Poisson(32) max-degree << 96

// ---------------- static scratch (no allocations allowed) ------------------
__device__ __half g_xw[(size_t)N_NODES * OUT_DIM];     // 25.6 MB  x @ W (fp16)
__device__ int2   g_bucket[(size_t)N_NODES * CAP];     // 76.8 MB  {src, w bits}
__device__ int    g_cur[N_NODES];                      // cursors; zero-init, gather
                                                       // self-resets -> no zcur kernel

// ---------------------------------------------------------------------------
// TF32 tensor-core GEMM  xw[M,128] = x[M,256] @ W[256,128], fp16 output.
// BM=128, BN=128, BK=32; 8 warps = 2M x 4N; warp tile 64x32.
// cp.async DOUBLE-BUFFERED smem (raw fp32), cvt.rna.tf32 at fragment load.
// (Proven R13/R14 config, 91.7us measured.)
// ---------------------------------------------------------------------------
#define BM 128
#define BK 32
#define A_PITCH 36
#define B_PITCH 136
#define A_WORDS (BM * A_PITCH)              // 4608
#define B_WORDS (BK * B_PITCH)              // 4352
#define BUF_WORDS (A_WORDS + B_WORDS)       // 8960
#define GEMM_SMEM_BYTES (2 * BUF_WORDS * 4) // 71680

__device__ __forceinline__ uint32_t f2tf32(float f) {
    uint32_t r;
    asm("cvt.rna.tf32.f32 %0, %1;" : "=r"(r) : "f"(f));
    return r;
}

__device__ __forceinline__ void cp16(uint32_t dst_smem, const void* src, bool pred) {
    asm volatile("cp.async.cg.shared.global [%0], [%1], 16, %2;"
                 :: "r"(dst_smem), "l"(src), "r"(pred ? 16 : 0));
}

__global__ __launch_bounds__(256, 2) void gemm_tf32_kernel(const float* __restrict__ x,
                                                           const float* __restrict__ w) {
    extern __shared__ float sm[];

    const int tid    = threadIdx.x;
    const int wid    = tid >> 5;
    const int lane   = tid & 31;
    const int grp    = lane >> 2;
    const int qid    = lane & 3;
    const int warp_m = wid >> 2;
    const int warp_n = wid & 3;
    const int m0     = blockIdx.x * BM;
    const int m_base = warp_m * 64;
    const int n_base = warp_n * 32;

    const int a_kc = tid & 7;
    const int b_nc = tid & 31;

    auto issue_tile = [&](int k0, int buf) {
        float* base = sm + buf * BUF_WORDS;
        uint32_t a_base = (uint32_t)__cvta_generic_to_shared(base);
        uint32_t b_base = (uint32_t)__cvta_generic_to_shared(base + A_WORDS);
#pragma unroll
        for (int it = 0; it < 4; it++) {
            int s   = tid + it * 256;
            int m   = s >> 3;
            int row = m0 + m;
            bool ok = row < N_NODES;
            int srow = ok ? row : (N_NODES - 1);
            cp16(a_base + (uint32_t)(m * A_PITCH + a_kc * 4) * 4,
                 x + (size_t)srow * IN_DIM + k0 + a_kc * 4, ok);
        }
#pragma unroll
        for (int it = 0; it < 4; it++) {
            int s = tid + it * 256;
            int k = s >> 5;
            cp16(b_base + (uint32_t)(k * B_PITCH + b_nc * 4) * 4,
                 w + (size_t)(k0 + k) * OUT_DIM + b_nc * 4, true);
        }
        asm volatile("cp.async.commit_group;");
    };

    float c[4][4][4];
#pragma unroll
    for (int mt = 0; mt < 4; mt++)
#pragma unroll
        for (int nt = 0; nt < 4; nt++)
#pragma unroll
            for (int r = 0; r < 4; r++) c[mt][nt][r] = 0.f;

    issue_tile(0, 0);
    asm volatile("cp.async.wait_group 0;");
    __syncthreads();

    int buf = 0;
    for (int k0 = 0; k0 < IN_DIM; k0 += BK) {
        const bool more = (k0 + BK) < IN_DIM;
        if (more) issue_tile(k0 + BK, buf ^ 1);

        const float* A = sm + buf * BUF_WORDS;
        const float* B = A + A_WORDS;

#pragma unroll
        for (int ks = 0; ks < 4; ks++) {
            const int kk = ks * 8;
            uint32_t a[4][4], b[4][2];
#pragma unroll
            for (int mt = 0; mt < 4; mt++) {
                int row = m_base + mt * 16 + grp;
                a[mt][0] = f2tf32(A[row * A_PITCH + kk + qid]);
                a[mt][1] = f2tf32(A[(row + 8) * A_PITCH + kk + qid]);
                a[mt][2] = f2tf32(A[row * A_PITCH + kk + qid + 4]);
                a[mt][3] = f2tf32(A[(row + 8) * A_PITCH + kk + qid + 4]);
            }
#pragma unroll
            for (int nt = 0; nt < 4; nt++) {
                int col = n_base + nt * 8 + grp;
                b[nt][0] = f2tf32(B[(kk + qid) * B_PITCH + col]);
                b[nt][1] = f2tf32(B[(kk + qid + 4) * B_PITCH + col]);
            }
#pragma unroll
            for (int mt = 0; mt < 4; mt++)
#pragma unroll
                for (int nt = 0; nt < 4; nt++) {
                    asm volatile(
                        "mma.sync.aligned.m16n8k8.row.col.f32.tf32.tf32.f32 "
                        "{%0,%1,%2,%3}, {%4,%5,%6,%7}, {%8,%9}, {%0,%1,%2,%3};\n"
                        : "+f"(c[mt][nt][0]), "+f"(c[mt][nt][1]),
                          "+f"(c[mt][nt][2]), "+f"(c[mt][nt][3])
                        : "r"(a[mt][0]), "r"(a[mt][1]), "r"(a[mt][2]), "r"(a[mt][3]),
                          "r"(b[nt][0]), "r"(b[nt][1]));
                }
        }
        if (more) {
            asm volatile("cp.async.wait_group 0;");
            __syncthreads();
            buf ^= 1;
        }
    }

#pragma unroll
    for (int mt = 0; mt < 4; mt++) {
        int r0 = m0 + m_base + mt * 16 + grp;
        int r1 = r0 + 8;
#pragma unroll
        for (int nt = 0; nt < 4; nt++) {
            int col = n_base + nt * 8 + qid * 2;
            if (r0 < N_NODES)
                *(__half2*)(g_xw + (size_t)r0 * OUT_DIM + col) =
                    __floats2half2_rn(c[mt][nt][0], c[mt][nt][1]);
            if (r1 < N_NODES)
                *(__half2*)(g_xw + (size_t)r1 * OUT_DIM + col) =
                    __floats2half2_rn(c[mt][nt][2], c[mt][nt][3]);
        }
    }
}

// ---------------------------------------------------------------------------
// Fill pass: cursors are zero on entry (zero-init at load; gather resets
// them at the end of every call). No separate zeroing kernel needed.
// ---------------------------------------------------------------------------
__global__ void fill_kernel(const int* __restrict__ esrc,
                            const int* __restrict__ edst,
                            const float* __restrict__ ew) {
    int e = blockIdx.x * blockDim.x + threadIdx.x;
    if (e < N_EDGES) {
        int d   = edst[e];
        int pos = atomicAdd(&g_cur[d], 1);
        if (pos < CAP)   // safety clamp; statistically unreachable
            g_bucket[(size_t)d * CAP + pos] = make_int2(esrc[e], __float_as_int(ew[e]));
    }
}

// ---------------------------------------------------------------------------
// Aggregate (proven R14 version, 73.0us): one warp per dst node; 16 lanes x
// 16B per row; edge-pair loop UNROLLED x2 -> 2 independent LDG.128 in flight.
// Packed fma.rn.f32x2; zero-weight padding; cross-half shfl reduction;
// fused ReLU. Lane 0 self-resets g_cur[node] for the next call. No atomics.
// ---------------------------------------------------------------------------
__global__ __launch_bounds__(256) void gather_kernel(float* __restrict__ out) {
    const int node = blockIdx.x * 8 + (threadIdx.x >> 5);
    const int lane = threadIdx.x & 31;
    if (node >= N_NODES) return;

    const int h   = lane >> 4;       // which edge of the pair
    const int sub = lane & 15;       // 16B chunk within the row

    const int cnt = min(g_cur[node], CAP);
    if (lane == 0 && cnt != 0) g_cur[node] = 0;   // self-reset for next call
    const int2* bkt = g_bucket + (size_t)node * CAP;

    unsigned long long acc[4] = {0ull, 0ull, 0ull, 0ull};   // 4 x f32x2

    for (int base = 0; base < cnt; base += 32) {
        const int n = min(32, cnt - base);
        int   mysrc = 0;
        float myw   = 0.f;                   // zero weight = inert padding
        if (lane < n) {
            int2 rec = bkt[base + lane];
            mysrc = rec.x;
            myw   = __int_as_float(rec.y);
        }
        const int jmax = (n + 1) >> 1;       // edge-pairs in this batch
        int jj = 0;
        // ---- unrolled x2: two independent gathers in flight ----
        for (; jj + 2 <= jmax; jj += 2) {
            const int   s0 = __shfl_sync(0xffffffff, mysrc, 2 * jj + h);
            const float w0 = __shfl_sync(0xffffffff, myw,  2 * jj + h);
            const int   s1 = __shfl_sync(0xffffffff, mysrc, 2 * jj + 2 + h);
            const float w1 = __shfl_sync(0xffffffff, myw,  2 * jj + 2 + h);

            const float4 r0 = *(const float4*)(g_xw + (size_t)s0 * OUT_DIM + sub * 8);
            const float4 r1 = *(const float4*)(g_xw + (size_t)s1 * OUT_DIM + sub * 8);

            unsigned long long ww0, ww1;
            asm("mov.b64 %0, {%1, %1};" : "=l"(ww0) : "f"(w0));
            asm("mov.b64 %0, {%1, %1};" : "=l"(ww1) : "f"(w1));

            const __half2* h0 = (const __half2*)&r0;
            const __half2* h1 = (const __half2*)&r1;
#pragma unroll
            for (int r = 0; r < 4; r++) {
                float2 v = __half22float2(h0[r]);
                unsigned long long vv;
                asm("mov.b64 %0, {%1, %2};" : "=l"(vv) : "f"(v.x), "f"(v.y));
                asm("fma.rn.f32x2 %0, %1, %2, %0;" : "+l"(acc[r]) : "l"(vv), "l"(ww0));
            }
#pragma unroll
            for (int r = 0; r < 4; r++) {
                float2 v = __half22float2(h1[r]);
                unsigned long long vv;
                asm("mov.b64 %0, {%1, %2};" : "=l"(vv) : "f"(v.x), "f"(v.y));
                asm("fma.rn.f32x2 %0, %1, %2, %0;" : "+l"(acc[r]) : "l"(vv), "l"(ww1));
            }
        }
        // ---- tail edge-pair ----
        for (; jj < jmax; jj++) {
            const int   src = __shfl_sync(0xffffffff, mysrc, 2 * jj + h);
            const float wsc = __shfl_sync(0xffffffff, myw,  2 * jj + h);
            unsigned long long ww;
            asm("mov.b64 %0, {%1, %1};" : "=l"(ww) : "f"(wsc));
            const float4 raw = *(const float4*)(g_xw + (size_t)src * OUT_DIM + sub * 8);
            const __half2* hp = (const __half2*)&raw;
#pragma unroll
            for (int r = 0; r < 4; r++) {
                float2 v = __half22float2(hp[r]);
                unsigned long long vv;
                asm("mov.b64 %0, {%1, %2};" : "=l"(vv) : "f"(v.x), "f"(v.y));
                asm("fma.rn.f32x2 %0, %1, %2, %0;" : "+l"(acc[r]) : "l"(vv), "l"(ww));
            }
        }
    }

    // cross-half reduction (lane i += lane i+16), ReLU, store by lanes 0-15
    float lo[4], hi[4];
#pragma unroll
    for (int r = 0; r < 4; r++) {
        float2 a = *(float2*)&acc[r];
        a.x += __shfl_xor_sync(0xffffffff, a.x, 16);
        a.y += __shfl_xor_sync(0xffffffff, a.y, 16);
        lo[r] = fmaxf(a.x, 0.f);
        hi[r] = fmaxf(a.y, 0.f);
    }
    if (h == 0) {
        float* o = out + (size_t)node * OUT_DIM + sub * 8;
        *(float4*)(o + 0) = make_float4(lo[0], hi[0], lo[1], hi[1]);
        *(float4*)(o + 4) = make_float4(lo[2], hi[2], lo[3], hi[3]);
    }
}

// ---------------------------------------------------------------------------
extern "C" void kernel_launch(void* const* d_in, const int* in_sizes, int n_in,
                              void* d_out, int out_size) {
    const float* x  = (const float*)d_in[0];       // [100000, 256] f32
    const float* w  = (const float*)d_in[1];       // [256, 128]    f32
    const float* ew = (const float*)d_in[2];       // [3.2M]        f32
    const int*   es = (const int*)d_in[3];         // [3.2M]        i32
    const int*   ed = (const int*)d_in[4];         // [3.2M]        i32
    float* out = (float*)d_out;                    // [100000, 128] f32

    const int eBlocks = (N_EDGES + 255) / 256;     // 12500
    const int gBlocks = (N_NODES + BM - 1) / BM;   // 782
    const int aBlocks = (N_NODES + 7) / 8;         // 12500 (8 warps/block)

    // static side stream + events for GEMM || bucket-build overlap
    static cudaStream_t side = nullptr;
    static cudaEvent_t  evFork = nullptr, evJoin = nullptr;
    if (!side) {
        cudaStreamCreateWithFlags(&side, cudaStreamNonBlocking);
        cudaEventCreateWithFlags(&evFork, cudaEventDisableTiming);
        cudaEventCreateWithFlags(&evJoin, cudaEventDisableTiming);
        cudaFuncSetAttribute(gemm_tf32_kernel,
                             cudaFuncAttributeMaxDynamicSharedMemorySize,
                             GEMM_SMEM_BYTES);
    }

    // fork: GEMM on side stream
    cudaEventRecord(evFork, 0);
    cudaStreamWaitEvent(side, evFork, 0);
    gemm_tf32_kernel<<<gBlocks, 256, GEMM_SMEM_BYTES, side>>>(x, w);
    cudaEventRecord(evJoin, side);

    // bucket build on main stream (cursors already zero; fill only)
    fill_kernel<<<eBlocks, 256>>>(es, ed, ew);

    // join: gather needs both g_xw (side) and buckets (main)
    cudaStreamWaitEvent(0, evJoin, 0);
    gather_kernel<<<aBlocks, 256>>>(out);
}